// round 16
// baseline (speedup 1.0000x reference)
#include <cuda_runtime.h>

#define BDIM 4096   // batch rows
#define IDIM 4096   // in features
#define ODIM 4096   // out features

// Scratch (allocation-free rule: __device__ global)
__device__ float g_wsb[ODIM];   // bias[o] * sum_i weight[o,i]

// ---------------------------------------------------------------------------
// Kernel 1: wsb[o] = bias[o] * sum_i weight[o,i]
// 4096 blocks x 128 threads, plain LDG.128 — measured at the 6.9 TB/s chip
// ceiling while also draining the previous replay's L2-resident output
// writes. Unchanged (proven optimal).
// ---------------------------------------------------------------------------
__global__ __launch_bounds__(128) void wsum_kernel(
    const float* __restrict__ weight,
    const float* __restrict__ bias)
{
    const int row = blockIdx.x;
    const int tid = threadIdx.x;
    const float4* src = reinterpret_cast<const float4*>(
        weight + (size_t)row * IDIM);

    float s = 0.0f;
#pragma unroll
    for (int i = 0; i < 8; i++) {
        float4 v = src[tid + i * 128];
        s += (v.x + v.y) + (v.z + v.w);
    }

#pragma unroll
    for (int off = 16; off > 0; off >>= 1)
        s += __shfl_down_sync(0xFFFFFFFFu, s, off);

    __shared__ float warp_sums[4];
    if ((tid & 31) == 0) warp_sums[tid >> 5] = s;
    __syncthreads();

    if (tid == 0) {
        float total = (warp_sums[0] + warp_sums[1]) +
                      (warp_sums[2] + warp_sums[3]);
        g_wsb[row] = total * __ldg(&bias[row]);
    }
}

// ---------------------------------------------------------------------------
// Kernel 2 (warp-autonomous fused): ONE WARP PER ROW, zero block barriers.
// Each lane covers 32 float4 (1024 float4/row / 32 lanes) — FIXED from R15
// where only 8 were covered.
//   reduce: 4 batches x 8 independent LDG.128 (4 KB/warp in flight per batch)
//   butterfly shfl: all lanes end with the full row sum
//   store : 32 x (2 L1-hit loads + plain STG.128 -> L2)
// No __syncthreads anywhere: the ~28 warps/SM drift into staggered phases, so
// some warps' DRAM load batches always overlap other warps' L1-bound store
// phases — the property that lets wsum hit 6.9 TB/s and that every barriered
// fused variant (R5/R13/R14: 3.2-3.5 TB/s) lacked.
// ---------------------------------------------------------------------------
__global__ __launch_bounds__(256) void fused_kernel(
    const float* __restrict__ input,
    const float* __restrict__ bias,
    float* __restrict__ out)
{
    const int wid = threadIdx.x >> 5;
    const int lid = threadIdx.x & 31;
    const int row = blockIdx.x * 8 + wid;

    const float4* src = reinterpret_cast<const float4*>(
        input + (size_t)row * IDIM);

    // Reduce phase: 32 float4/lane in 4 batches of 8 (keeps 8 LDG.128 in
    // flight per batch while the previous batch's adds retire).
    float s = 0.0f;
#pragma unroll
    for (int b = 0; b < 4; b++) {
        float4 v[8];
#pragma unroll
        for (int i = 0; i < 8; i++)
            v[i] = src[lid + (b * 8 + i) * 32];
#pragma unroll
        for (int i = 0; i < 8; i++)
            s += (v[i].x + v[i].y) + (v[i].z + v[i].w);
    }

    // Butterfly reduce: every lane ends with the full row sum.
#pragma unroll
    for (int off = 16; off > 0; off >>= 1)
        s += __shfl_xor_sync(0xFFFFFFFFu, s, off);
    const float xs = s;

    // Store phase: full row, 32 float4/lane. bias/wsb are 16 KB each ->
    // L1-resident after first touch; loads are L1 hits.
    float4* dst = reinterpret_cast<float4*>(out + (size_t)row * ODIM);
    const float4* bi4 = reinterpret_cast<const float4*>(bias);
    const float4* ws4 = reinterpret_cast<const float4*>(g_wsb);

#pragma unroll 8
    for (int j = 0; j < 32; j++) {
        const int c = lid + j * 32;
        float4 b = bi4[c];
        float4 w = ws4[c];
        float4 o;
        o.x = fmaf(xs, b.x, w.x);
        o.y = fmaf(xs, b.y, w.y);
        o.z = fmaf(xs, b.z, w.z);
        o.w = fmaf(xs, b.w, w.w);
        dst[c] = o;                              // plain STG.128 -> L2
    }
}

extern "C" void kernel_launch(void* const* d_in, const int* in_sizes, int n_in,
                              void* d_out, int out_size)
{
    const float* input  = (const float*)d_in[0];
    const float* weight = (const float*)d_in[1];
    const float* bias   = (const float*)d_in[2];
    float* out = (float*)d_out;

    wsum_kernel<<<ODIM, 128>>>(weight, bias);
    fused_kernel<<<BDIM / 8, 256>>>(input, bias, out);
}

// round 17
// speedup vs baseline: 1.0491x; 1.0491x over previous
#include <cuda_runtime.h>
#include <cstdint>

#define BDIM 4096   // batch rows
#define IDIM 4096   // in features
#define ODIM 4096   // out features
#define EXP_ROWS 8  // rows per expand block

// Scratch (allocation-free rule: __device__ globals)
__device__ float g_xs[BDIM];    // sum_i input[b,i]
__device__ float g_wsb[ODIM];   // bias[o] * sum_i weight[o,i]

// ---------------------------------------------------------------------------
// Kernel 1: row sums for BOTH tensors (R4 structure — measured 6.9 TB/s while
// also draining the previous replay's L2-resident output writes). Unchanged.
// ---------------------------------------------------------------------------
__global__ __launch_bounds__(128) void rowsum_kernel(
    const float* __restrict__ input,
    const float* __restrict__ weight,
    const float* __restrict__ bias)
{
    const int bid = blockIdx.x;
    const int tid = threadIdx.x;

    const bool is_w = (bid >= BDIM);
    const int  row  = is_w ? (bid - BDIM) : bid;
    const float4* src = reinterpret_cast<const float4*>(
        (is_w ? weight : input) + (size_t)row * IDIM);

    float s = 0.0f;
#pragma unroll
    for (int i = 0; i < 8; i++) {
        float4 v = src[tid + i * 128];           // plain LDG.128, high MLP
        s += (v.x + v.y) + (v.z + v.w);
    }

#pragma unroll
    for (int off = 16; off > 0; off >>= 1)
        s += __shfl_down_sync(0xFFFFFFFFu, s, off);

    __shared__ float warp_sums[4];
    if ((tid & 31) == 0) warp_sums[tid >> 5] = s;
    __syncthreads();

    if (tid == 0) {
        float total = (warp_sums[0] + warp_sums[1]) +
                      (warp_sums[2] + warp_sums[3]);
        if (is_w) g_wsb[row] = total * __ldg(&bias[row]);
        else      g_xs[row]  = total;
    }
}

// ---------------------------------------------------------------------------
// Kernel 2: TMA-store expand. out[b,:] = xs[b]*bias + wsb.
// 512 blocks x 256 threads, 8 rows/block, double-buffered 2x16KB smem.
// KEY IDEA: stores never touch the L1tex global pipeline (the bottleneck in
// every prior expand/fused variant, 13-22us). Threads write rows into SHARED
// memory (separate 128 B/cyc/SM crossbar) and one thread fires a 16 KB
// cp.async.bulk shared->global per row — the TMA engine moves data to L2 at
// the ~6300 B/cyc chip cap: 64 MB in ~5-6us. Writes absorb into L2 and drain
// during the next replay's rowsum read window, exactly as before.
// bias/wsb are hoisted into registers once per block (16 MB total L2 re-read
// across the grid instead of 128 MB if reloaded per row).
// ---------------------------------------------------------------------------
__global__ __launch_bounds__(256) void expand_tma_kernel(
    const float* __restrict__ bias,
    float* __restrict__ out)
{
    __shared__ __align__(16) float4 buf[2][1024];   // 2 x 16 KB row buffers

    const int tid  = threadIdx.x;
    const int row0 = blockIdx.x * EXP_ROWS;

    // Hoist bias/wsb for this thread's 4 float4 columns into registers.
    const float4* bi4 = reinterpret_cast<const float4*>(bias);
    const float4* ws4 = reinterpret_cast<const float4*>(g_wsb);
    float4 breg[4], wreg[4];
#pragma unroll
    for (int i = 0; i < 4; i++) {
        breg[i] = bi4[tid + i * 256];
        wreg[i] = ws4[tid + i * 256];
    }

    uint32_t sbase[2];
    {
        uint64_t a0, a1;
        asm("{ .reg .u64 t; cvta.to.shared.u64 t, %2; mov.u64 %0, t;"
            "  cvta.to.shared.u64 t, %3; mov.u64 %1, t; }"
            : "=l"(a0), "=l"(a1) : "l"(&buf[0][0]), "l"(&buf[1][0]));
        sbase[0] = (uint32_t)a0;
        sbase[1] = (uint32_t)a1;
    }

#pragma unroll
    for (int r = 0; r < EXP_ROWS; r++) {
        const int p = r & 1;

        // Before reusing buffer p, make sure its previous bulk-store (group
        // r-2) has been consumed: allow at most 1 group (r-1) in flight.
        if (r >= 2) {
            if (tid == 0)
                asm volatile("cp.async.bulk.wait_group 1;" ::: "memory");
            __syncthreads();
        }

        const float xs = g_xs[row0 + r];          // uniform, L2/L1-hot

#pragma unroll
        for (int i = 0; i < 4; i++) {
            const int c = tid + i * 256;
            float4 o;
            o.x = fmaf(xs, breg[i].x, wreg[i].x);
            o.y = fmaf(xs, breg[i].y, wreg[i].y);
            o.z = fmaf(xs, breg[i].z, wreg[i].z);
            o.w = fmaf(xs, breg[i].w, wreg[i].w);
            buf[p][c] = o;                        // STS.128, conflict-free
        }
        __syncthreads();                          // row complete in smem

        if (tid == 0) {
            // Order the CTA's generic smem writes before the async-proxy read.
            asm volatile("fence.proxy.async.shared::cta;" ::: "memory");
            float* gdst = out + (size_t)(row0 + r) * ODIM;
            asm volatile(
                "cp.async.bulk.global.shared::cta.bulk_group [%0], [%1], %2;"
                :: "l"(gdst), "r"(sbase[p]), "r"((int)(ODIM * 4))
                : "memory");
            asm volatile("cp.async.bulk.commit_group;" ::: "memory");
        }
    }

    // Drain all bulk stores before the CTA exits (smem is reclaimed on exit).
    if (tid == 0)
        asm volatile("cp.async.bulk.wait_group 0;" ::: "memory");
}

extern "C" void kernel_launch(void* const* d_in, const int* in_sizes, int n_in,
                              void* d_out, int out_size)
{
    const float* input  = (const float*)d_in[0];
    const float* weight = (const float*)d_in[1];
    const float* bias   = (const float*)d_in[2];
    float* out = (float*)d_out;

    rowsum_kernel<<<BDIM + ODIM, 128>>>(input, weight, bias);
    expand_tma_kernel<<<BDIM / EXP_ROWS, 256>>>(bias, out);
}